// round 6
// baseline (speedup 1.0000x reference)
#include <cuda_runtime.h>
#include <math.h>

#define NN 10000
#define NE 320000
#define NLAY 4
#define NT 100
#define MR_ 2.5f
#define PI_F 3.14159265358979f
#define SQRT3_F 1.7320508075688772f
#define INV_SQRT2 0.7071067811865476f
#define INV_SQRT6 0.4082482904638630f
#define C_S 0.3826834323650898f
#define C_X 0.9238795325112867f
#define EF_C 2.5298221281347035f

/* ---------- static device scratch ---------- */
__device__ float g_K[32];
__device__ float g_x[NN * 6];
__device__ float g_ys[NN * 64], g_ysold[NN * 64], g_yv[NN * 48], g_yvold[NN * 48];
__device__ float g_fs[NN * 64], g_fvv[NN * 48];
__device__ float g_scs[NN * 80], g_scv[NN * 48];
__device__ float g_sis[NN * 64], g_siv[NN * 48];
__device__ float g_mids[NN * 16], g_midv[NN * 240];
/* per-(layer,type) contracted fctp weights, layout [l][t][i*O+o], norms folded */
__device__ float cw_l1s[NLAY * NT * 4096];
__device__ float cw_l1v[NLAY * NT * 256];
__device__ float cw_scs[NLAY * NT * 5120];
__device__ float cw_scv[NLAY * NT * 256];
__device__ float cw_l2s[NLAY * NT * 1280];
__device__ float cw_l2v[NLAY * NT * 1280];

__device__ __forceinline__ float silu_(float x) { return x / (1.f + __expf(-x)); }
__device__ __forceinline__ float sigm_(float x) { return 1.f / (1.f + __expf(-x)); }
__device__ __forceinline__ float cutf_(float r) {
    float u = 2.f * (r / MR_) - 2.f;
    if (u > 0.f) return 0.f;
    if (u < -1.f) return 1.f;
    return 0.5f * (1.f - __cosf(PI_F * u));
}

/* ---------- K = semi_unitary(PU_K) ---------- */
__global__ void k_newton(const float* __restrict__ PU) {
    if (threadIdx.x || blockIdx.x) return;
    float K0[16], K1[16], nrm = 0.f;
    for (int u = 0; u < 16; u++) {
        K0[u] = PU[2 * u]; K1[u] = PU[2 * u + 1];
        nrm += K0[u] * K0[u] + K1[u] * K1[u];
    }
    nrm = sqrtf(nrm);
    for (int u = 0; u < 16; u++) { K0[u] /= nrm; K1[u] /= nrm; }
    for (int it = 0; it < 10; it++) {
        float m00 = 0.f, m01 = 0.f, m11 = 0.f;
        for (int u = 0; u < 16; u++) {
            m00 += K0[u] * K0[u]; m01 += K0[u] * K1[u]; m11 += K1[u] * K1[u];
        }
        for (int u = 0; u < 16; u++) {
            float a = 1.5f * K0[u] - 0.5f * (K0[u] * m00 + K1[u] * m01);
            float b = 1.5f * K1[u] - 0.5f * (K0[u] * m01 + K1[u] * m11);
            K0[u] = a; K1[u] = b;
        }
    }
    for (int u = 0; u < 16; u++) { g_K[2 * u] = K0[u]; g_K[2 * u + 1] = K1[u]; }
}

/* ---------- precontract fctp weights over node-attr embedding ---------- */
__global__ void k_contract(const float* __restrict__ W, const float* __restrict__ emb,
                           int O, int I, float norm, int sel) {
    float* out;
    switch (sel) {
        case 0: out = cw_l1s; break; case 1: out = cw_l1v; break;
        case 2: out = cw_scs; break; case 3: out = cw_scv; break;
        case 4: out = cw_l2s; break; default: out = cw_l2v; break;
    }
    int idx = blockIdx.x * 256 + threadIdx.x;
    int total = NLAY * NT * O * I;
    if (idx >= total) return;
    int o = idx % O, i = (idx / O) % I, t = (idx / (O * I)) % NT, l = idx / (O * I * NT);
    const float* wp = W + (((size_t)(l * O + o) * I + i) * 32);
    const float* ep = emb + t * 32;
    float s = 0.f;
#pragma unroll
    for (int k = 0; k < 32; k++) s += ep[k] * wp[k];
    out[(((size_t)l * NT + t) * I + i) * O + o] = s * norm;
}

/* ---------- init: scalars zero, vectors = uplift ---------- */
__global__ void k_init(const float* __restrict__ x) {
    int tid = blockIdx.x * 256 + threadIdx.x;
    if (tid < NN * 64) { g_ys[tid] = 0.f; g_ysold[tid] = 0.f; }
    if (tid < NN * 48) {
        int n = tid / 48, r = tid - 48 * n, u = r / 3, m = r - 3 * u;
        float v = g_K[2 * u] * x[n * 6 + m] + g_K[2 * u + 1] * x[n * 6 + 3 + m];
        g_yv[tid] = v; g_yvold[tid] = v;
    }
    if (tid < NN * 6) g_x[tid] = x[tid];
}

/* ---------- node kernel 1: lin1 / sc / si ---------- */
__global__ void k_node1(int l, const int* __restrict__ ntype,
                        const float* __restrict__ siWs, const float* __restrict__ siWv) {
    int n = blockIdx.x, tid = threadIdx.x;
    __shared__ float sy[64], sv[48];
    if (tid < 64) sy[tid] = g_ys[n * 64 + tid];
    if (tid < 48) sv[tid] = g_yv[n * 48 + tid];
    __syncthreads();
    int t = ntype[n];
    size_t base = (size_t)l * NT + t;
    const float* w = cw_scs + base * 5120;
    float acc = 0.f;
#pragma unroll 8
    for (int i = 0; i < 64; i++) acc += sy[i] * w[i * 80 + tid];
    g_scs[n * 80 + tid] = acc;
    if (tid < 64) {
        w = cw_l1s + base * 4096;
        acc = 0.f;
#pragma unroll 8
        for (int i = 0; i < 64; i++) acc += sy[i] * w[i * 64 + tid];
        g_fs[n * 64 + tid] = acc;
        const float* ws = siWs + (size_t)l * 4096 + tid * 64;
        acc = 0.f;
#pragma unroll 8
        for (int i = 0; i < 64; i++) acc += sy[i] * ws[i];
        g_sis[n * 64 + tid] = acc * 0.125f;
    }
    if (tid < 48) {
        int u = tid / 3, m = tid - 3 * u;
        w = cw_l1v + base * 256;
        acc = 0.f;
#pragma unroll
        for (int i = 0; i < 16; i++) acc += w[i * 16 + u] * sv[3 * i + m];
        g_fvv[n * 48 + tid] = acc;
        w = cw_scv + base * 256;
        acc = 0.f;
#pragma unroll
        for (int i = 0; i < 16; i++) acc += w[i * 16 + u] * sv[3 * i + m];
        g_scv[n * 48 + tid] = acc;
        const float* wv = siWv + (size_t)l * 256;
        acc = 0.f;
#pragma unroll
        for (int i = 0; i < 16; i++) acc += wv[u * 16 + i] * sv[3 * i + m];
        g_siv[n * 48 + tid] = acc * 0.25f;
    }
}

/* ---------- zero mid accumulators ---------- */
__global__ void k_zero() {
    int tid = blockIdx.x * 256 + threadIdx.x;
    if (tid < NN * 240) g_midv[tid] = 0.f;
    if (tid < NN * 16) g_mids[tid] = 0.f;
}

/* ---------- fused edge kernel: geom + radial MLP + TP + scatter ---------- */
#define WSLOT 208
__global__ void __launch_bounds__(256)
k_edge(const int* __restrict__ esrc, const int* __restrict__ edst,
       const float* __restrict__ W1, const float* __restrict__ b1,
       const float* __restrict__ W2, const float* __restrict__ b2,
       const float* __restrict__ W3, const float* __restrict__ b3) {
    extern __shared__ float sm[];
    float* sW1 = sm;            /* 1024 */
    float* sB1 = sm + 1024;     /* 64 */
    float* sW2 = sm + 1088;     /* 4096 */
    float* sB2 = sm + 5184;     /* 64 */
    float* sW3 = sm + 5248;     /* 12288 */
    float* sB3 = sm + 17536;    /* 192 */
    int tid = threadIdx.x, wid = tid >> 5, lane = tid & 31;
    float* wsm = sm + 17728 + wid * WSLOT;
    float* ef = wsm;            /* 16 */
    float* h1 = wsm + 16;       /* 64 */
    float* h2s = wsm + 80;      /* 64 */
    float* aa = wsm + 144;      /* 6 */
    float* vs = wsm + 150;      /* 48 */
    float* dd = wsm + 198;      /* 6 */

    for (int i = tid; i < 1024; i += 256) sW1[i] = W1[i];
    for (int i = tid; i < 4096; i += 256) sW2[i] = W2[i];
    for (int i = tid; i < 12288; i += 256) sW3[i] = W3[i];
    if (tid < 64) { sB1[tid] = b1[tid]; sB2[tid] = b2[tid]; }
    if (tid < 192) sB3[tid] = b3[tid];
    __syncthreads();

    for (int e = blockIdx.x * 8 + wid; e < NE; e += gridDim.x * 8) {
        __syncwarp();
        int src = esrc[e], dst = edst[e];
        if (lane < 6) dd[lane] = g_x[src * 6 + lane] - g_x[dst * 6 + lane];
        __syncwarp();
        float d0 = dd[0], d1 = dd[1], d2 = dd[2], d3 = dd[3], d4 = dd[4], d5 = dd[5];
        float rr = sqrtf(d0 * d0 + d1 * d1 + d2 * d2);
        float rv = sqrtf(d3 * d3 + d4 * d4 + d5 * d5);
        float cr = cutf_(rr), cv = cutf_(rv);
        if (cr == 0.f && cv == 0.f) continue;
        if (lane < 3) aa[lane] = cr * SQRT3_F / rr * dd[lane];
        else if (lane < 6) aa[lane] = cv * SQRT3_F / rv * dd[lane];
        if (lane < 8) ef[lane] = EF_C * sinf((float)(lane + 1) * PI_F * rr / MR_) / rr;
        else if (lane < 16) ef[lane] = EF_C * sinf((float)(lane - 7) * PI_F * rv / MR_) / rv;
        __syncwarp();
        /* layer 1 */
        float a0 = sB1[lane], a1 = sB1[lane + 32];
#pragma unroll
        for (int k = 0; k < 16; k++) {
            float f = ef[k];
            a0 += f * sW1[k * 64 + lane]; a1 += f * sW1[k * 64 + lane + 32];
        }
        h1[lane] = silu_(a0); h1[lane + 32] = silu_(a1);
        __syncwarp();
        /* layer 2, plus stage v_src */
        a0 = sB2[lane]; a1 = sB2[lane + 32];
#pragma unroll 8
        for (int k = 0; k < 64; k++) {
            float f = h1[k];
            a0 += f * sW2[k * 64 + lane]; a1 += f * sW2[k * 64 + lane + 32];
        }
        h2s[lane] = silu_(a0); h2s[lane + 32] = silu_(a1);
        if (lane < 24) {
            vs[2 * lane] = g_fvv[src * 48 + 2 * lane];
            vs[2 * lane + 1] = g_fvv[src * 48 + 2 * lane + 1];
        }
        __syncwarp();
        /* layer 3: 6 w-outputs per lane */
        int o4, o5;
        if (lane < 16) { o4 = 128 + 2 * lane; o5 = o4 + 1; }
        else { o4 = 160 + 2 * (lane - 16); o5 = o4 + 1; }
        float wA0 = sB3[2 * lane], wA1 = sB3[2 * lane + 1];
        float wA2 = sB3[2 * lane + 64], wA3 = sB3[2 * lane + 65];
        float w4 = sB3[o4], w5 = sB3[o5];
#pragma unroll 8
        for (int k = 0; k < 64; k++) {
            float f = h2s[k];
            const float* r = &sW3[k * 192];
            wA0 += f * r[2 * lane]; wA1 += f * r[2 * lane + 1];
            wA2 += f * r[2 * lane + 64]; wA3 += f * r[2 * lane + 65];
            w4 += f * r[o4]; w5 += f * r[o5];
        }
        /* tensor products + scatter */
        float s0 = g_fs[src * 64 + lane], s1 = g_fs[src * 64 + lane + 32];
        float a00 = aa[0], a01 = aa[1], a02 = aa[2];
        float a10 = aa[3], a11 = aa[4], a12 = aa[5];
        float* mv = &g_midv[dst * 240];
        float c0 = s0 * INV_SQRT2;
        atomicAdd(&mv[3 * lane + 0], c0 * (wA0 * a00 + wA1 * a10));
        atomicAdd(&mv[3 * lane + 1], c0 * (wA0 * a01 + wA1 * a11));
        atomicAdd(&mv[3 * lane + 2], c0 * (wA0 * a02 + wA1 * a12));
        float c1 = s1 * INV_SQRT2;
        int u2 = lane + 32;
        atomicAdd(&mv[3 * u2 + 0], c1 * (wA2 * a00 + wA3 * a10));
        atomicAdd(&mv[3 * u2 + 1], c1 * (wA2 * a01 + wA3 * a11));
        atomicAdd(&mv[3 * u2 + 2], c1 * (wA2 * a02 + wA3 * a12));
        if (lane < 16) {
            float v0 = vs[3 * lane], v1 = vs[3 * lane + 1], v2 = vs[3 * lane + 2];
            float dA = v0 * a00 + v1 * a01 + v2 * a02;
            float dB = v0 * a10 + v1 * a11 + v2 * a12;
            atomicAdd(&g_mids[dst * 16 + lane], (w4 * dA + w5 * dB) * INV_SQRT6);
        } else {
            int u = lane - 16;
            float v0 = vs[3 * u], v1 = vs[3 * u + 1], v2 = vs[3 * u + 2];
            float cx0 = v1 * a02 - v2 * a01, cy0 = v2 * a00 - v0 * a02, cz0 = v0 * a01 - v1 * a00;
            float cx1 = v1 * a12 - v2 * a11, cy1 = v2 * a10 - v0 * a12, cz1 = v0 * a11 - v1 * a10;
            atomicAdd(&mv[(64 + u) * 3 + 0], 0.5f * (w4 * cx0 + w5 * cx1));
            atomicAdd(&mv[(64 + u) * 3 + 1], 0.5f * (w4 * cy0 + w5 * cy1));
            atomicAdd(&mv[(64 + u) * 3 + 2], 0.5f * (w4 * cz0 + w5 * cz1));
        }
    }
}

/* ---------- node kernel 2: lin2 + gate + leapfrog + project ---------- */
__global__ void k_node2(int l, const int* __restrict__ ntype,
                        const float* __restrict__ hv, const float* __restrict__ mixv) {
    int n = blockIdx.x, tid = threadIdx.x;
    __shared__ float smids[16], smidv[240], sg[80], snv[48];
    if (tid < 16) smids[tid] = g_mids[n * 16 + tid];
    for (int i = tid; i < 240; i += 80) smidv[i] = g_midv[n * 240 + i];
    __syncthreads();
    int t = ntype[n];
    size_t base = (size_t)l * NT + t;
    float h2 = hv[l] * hv[l], mx = mixv[l];
    const float* w = cw_l2s + base * 1280;
    float acc = 0.f;
#pragma unroll
    for (int i = 0; i < 16; i++) acc += smids[i] * w[i * 80 + tid];
    float conv_s = C_S * g_scs[n * 80 + tid] + C_X * acc;
    sg[tid] = conv_s;
    __syncthreads();
    if (tid < 64) {
        float gns = silu_(conv_s);
        float yo = g_ysold[n * 64 + tid], yc = g_ys[n * 64 + tid];
        float ns = 2.f * yc - yo + h2 * (mx * gns + (mx - 1.f) * g_sis[n * 64 + tid]);
        g_ysold[n * 64 + tid] = yc; g_ys[n * 64 + tid] = ns;
    }
    if (tid < 48) {
        int u = tid / 3, m = tid - 3 * u;
        const float* wv = cw_l2v + base * 1280;
        acc = 0.f;
#pragma unroll 8
        for (int i = 0; i < 80; i++) acc += wv[i * 16 + u] * smidv[3 * i + m];
        float conv_v = C_S * g_scv[n * 48 + tid] + C_X * acc;
        float gnv = sigm_(sg[64 + u]) * conv_v;
        float yo = g_yvold[n * 48 + tid], yc = g_yv[n * 48 + tid];
        float nv = 2.f * yc - yo + h2 * (mx * gnv + (mx - 1.f) * g_siv[n * 48 + tid]);
        g_yvold[n * 48 + tid] = yc; g_yv[n * 48 + tid] = nv;
        snv[tid] = nv;
    }
    __syncthreads();
    if (tid < 6) {
        int i = tid / 3, m = tid - 3 * i;
        float s = 0.f;
#pragma unroll
        for (int u = 0; u < 16; u++) s += g_K[2 * u + i] * snv[3 * u + m];
        g_x[n * 6 + tid] = s;
    }
}

__global__ void k_copyout(float* __restrict__ out) {
    int tid = blockIdx.x * 256 + threadIdx.x;
    if (tid < NN * 6) out[tid] = g_x[tid];
}

/* ---------- launch ---------- */
extern "C" void kernel_launch(void* const* d_in, const int* in_sizes, int n_in,
                              void* d_out, int out_size) {
    const float* x = (const float*)d_in[0];
    const int* node_attr = (const int*)d_in[2];
    const int* esrc = (const int*)d_in[3];
    const int* edst = (const int*)d_in[4];
    const float* emb = (const float*)d_in[5];
    const float* PU = (const float*)d_in[6];
    const float* hv = (const float*)d_in[7];
    const float* mixv = (const float*)d_in[8];
    const float* siWs = (const float*)d_in[9];
    const float* siWv = (const float*)d_in[10];
    const float* scWs = (const float*)d_in[11];
    const float* scWv = (const float*)d_in[12];
    const float* l1Ws = (const float*)d_in[13];
    const float* l1Wv = (const float*)d_in[14];
    const float* l2Ws = (const float*)d_in[15];
    const float* l2Wv = (const float*)d_in[16];
    const float* fW1 = (const float*)d_in[17];
    const float* fb1 = (const float*)d_in[18];
    const float* fW2 = (const float*)d_in[19];
    const float* fb2 = (const float*)d_in[20];
    const float* fW3 = (const float*)d_in[21];
    const float* fb3 = (const float*)d_in[22];

    static int smem_set = 0;
    const int EDGE_SMEM = (17728 + 8 * WSLOT) * 4;
    if (!smem_set) {
        cudaFuncSetAttribute(k_edge, cudaFuncAttributeMaxDynamicSharedMemorySize, EDGE_SMEM);
        smem_set = 1;
    }

    k_newton<<<1, 1>>>(PU);
    float n2048 = 1.f / sqrtf(2048.f), n512 = 1.f / sqrtf(512.f);
    float n2_l2s = 1.f / sqrtf(512.f * 32.f), n2_l2v = 1.f / sqrtf(2560.f * 32.f);
    k_contract<<<(NLAY * NT * 4096 + 255) / 256, 256>>>(l1Ws, emb, 64, 64, n2048, 0);
    k_contract<<<(NLAY * NT * 256 + 255) / 256, 256>>>(l1Wv, emb, 16, 16, n512, 1);
    k_contract<<<(NLAY * NT * 5120 + 255) / 256, 256>>>(scWs, emb, 80, 64, n2048, 2);
    k_contract<<<(NLAY * NT * 256 + 255) / 256, 256>>>(scWv, emb, 16, 16, n512, 3);
    k_contract<<<(NLAY * NT * 1280 + 255) / 256, 256>>>(l2Ws, emb, 80, 16, n2_l2s, 4);
    k_contract<<<(NLAY * NT * 1280 + 255) / 256, 256>>>(l2Wv, emb, 16, 80, n2_l2v, 5);
    k_init<<<(NN * 64 + 255) / 256, 256>>>(x);

    for (int l = 0; l < NLAY; l++) {
        k_node1<<<NN, 80>>>(l, node_attr, siWs, siWv);
        k_zero<<<(NN * 240 + 255) / 256, 256>>>();
        k_edge<<<296, 256, EDGE_SMEM>>>(esrc, edst,
                                        fW1 + (size_t)l * 1024, fb1 + (size_t)l * 64,
                                        fW2 + (size_t)l * 4096, fb2 + (size_t)l * 64,
                                        fW3 + (size_t)l * 12288, fb3 + (size_t)l * 192);
        k_node2<<<NN, 80>>>(l, node_attr, hv, mixv);
    }
    k_copyout<<<(NN * 6 + 255) / 256, 256>>>((float*)d_out);
}

// round 7
// speedup vs baseline: 1.1308x; 1.1308x over previous
#include <cuda_runtime.h>
#include <math.h>

#define NN 10000
#define NE 320000
#define NLAY 4
#define NT 100
#define MR_ 2.5f
#define PI_F 3.14159265358979f
#define SQRT3_F 1.7320508075688772f
#define INV_SQRT2 0.7071067811865476f
#define INV_SQRT6 0.4082482904638630f
#define C_S 0.3826834323650898f
#define C_X 0.9238795325112867f
#define EF_C 2.5298221281347035f

/* ---------- static device scratch ---------- */
__device__ float g_K[32];
__device__ float g_x[NN * 6];
__device__ float g_ys[NN * 64], g_ysold[NN * 64], g_yv[NN * 48], g_yvold[NN * 48];
__device__ float g_fs[NN * 64], g_fvv[NN * 48];
__device__ float g_scs[NN * 80], g_scv[NN * 48];
__device__ float g_sis[NN * 64], g_siv[NN * 48];
__device__ float g_mids[NN * 16], g_midv[NN * 240];
/* per-(layer,type) contracted fctp weights, layout [l][t][i*O+o], norms folded */
__device__ float cw_l1s[NLAY * NT * 4096];
__device__ float cw_l1v[NLAY * NT * 256];
__device__ float cw_scs[NLAY * NT * 5120];
__device__ float cw_scv[NLAY * NT * 256];
__device__ float cw_l2s[NLAY * NT * 1280];
__device__ float cw_l2v[NLAY * NT * 1280];

__device__ __forceinline__ float silu_(float x) { return x / (1.f + __expf(-x)); }
__device__ __forceinline__ float sigm_(float x) { return 1.f / (1.f + __expf(-x)); }
__device__ __forceinline__ float cutf_(float r) {
    float u = 2.f * (r / MR_) - 2.f;
    if (u > 0.f) return 0.f;
    if (u < -1.f) return 1.f;
    return 0.5f * (1.f - __cosf(PI_F * u));
}

/* ---------- packed f32x2 FFMA helpers (Blackwell) ---------- */
__device__ __forceinline__ unsigned long long pack2_(float f) {
    unsigned long long r;
    unsigned int fi = __float_as_uint(f);
    asm("mov.b64 %0, {%1, %1};" : "=l"(r) : "r"(fi));
    return r;
}
__device__ __forceinline__ void ffma2_(unsigned long long& acc, unsigned long long f2,
                                       unsigned long long w) {
    asm("fma.rn.f32x2 %0, %1, %2, %0;" : "+l"(acc) : "l"(f2), "l"(w));
}
__device__ __forceinline__ float2 unpack2_(unsigned long long v) {
    unsigned int lo, hi;
    asm("mov.b64 {%0, %1}, %2;" : "=r"(lo), "=r"(hi) : "l"(v));
    float2 r; r.x = __uint_as_float(lo); r.y = __uint_as_float(hi);
    return r;
}

/* ---------- K = semi_unitary(PU_K) ---------- */
__global__ void k_newton(const float* __restrict__ PU) {
    if (threadIdx.x || blockIdx.x) return;
    float K0[16], K1[16], nrm = 0.f;
    for (int u = 0; u < 16; u++) {
        K0[u] = PU[2 * u]; K1[u] = PU[2 * u + 1];
        nrm += K0[u] * K0[u] + K1[u] * K1[u];
    }
    nrm = sqrtf(nrm);
    for (int u = 0; u < 16; u++) { K0[u] /= nrm; K1[u] /= nrm; }
    for (int it = 0; it < 10; it++) {
        float m00 = 0.f, m01 = 0.f, m11 = 0.f;
        for (int u = 0; u < 16; u++) {
            m00 += K0[u] * K0[u]; m01 += K0[u] * K1[u]; m11 += K1[u] * K1[u];
        }
        for (int u = 0; u < 16; u++) {
            float a = 1.5f * K0[u] - 0.5f * (K0[u] * m00 + K1[u] * m01);
            float b = 1.5f * K1[u] - 0.5f * (K0[u] * m01 + K1[u] * m11);
            K0[u] = a; K1[u] = b;
        }
    }
    for (int u = 0; u < 16; u++) { g_K[2 * u] = K0[u]; g_K[2 * u + 1] = K1[u]; }
}

/* ---------- precontract fctp weights: W cached in regs, loop over types ----------
   grid = NLAY * (O*I/128), block = 128. Each thread owns one (i,o) column. */
__global__ void __launch_bounds__(128)
k_contract(const float* __restrict__ W, const float* __restrict__ emb,
           int O, int I, float norm, int sel) {
    float* out;
    switch (sel) {
        case 0: out = cw_l1s; break; case 1: out = cw_l1v; break;
        case 2: out = cw_scs; break; case 3: out = cw_scv; break;
        case 4: out = cw_l2s; break; default: out = cw_l2v; break;
    }
    __shared__ float es[NT * 32];
    int cols = O * I;
    int bpl = cols >> 7;
    int l = blockIdx.x / bpl;
    int c = ((blockIdx.x % bpl) << 7) + threadIdx.x;
    for (int j = threadIdx.x; j < NT * 32; j += 128) es[j] = emb[j];
    int i = c / O, o = c - i * O;
    const float4* wp = (const float4*)(W + (((size_t)(l * O + o) * I + i) * 32));
    float w[32];
#pragma unroll
    for (int q = 0; q < 8; q++) {
        float4 v = wp[q];
        w[4 * q] = v.x; w[4 * q + 1] = v.y; w[4 * q + 2] = v.z; w[4 * q + 3] = v.w;
    }
    __syncthreads();
    float* ob = out + (size_t)l * NT * cols + c;
    for (int t = 0; t < NT; t++) {
        const float* ep = es + t * 32;
        float a0 = 0.f, a1 = 0.f, a2 = 0.f, a3 = 0.f;
#pragma unroll
        for (int e = 0; e < 32; e += 4) {
            a0 += ep[e] * w[e]; a1 += ep[e + 1] * w[e + 1];
            a2 += ep[e + 2] * w[e + 2]; a3 += ep[e + 3] * w[e + 3];
        }
        ob[(size_t)t * cols] = ((a0 + a1) + (a2 + a3)) * norm;
    }
}

/* ---------- init: scalars zero, vectors = uplift ---------- */
__global__ void k_init(const float* __restrict__ x) {
    int tid = blockIdx.x * 256 + threadIdx.x;
    if (tid < NN * 64) { g_ys[tid] = 0.f; g_ysold[tid] = 0.f; }
    if (tid < NN * 48) {
        int n = tid / 48, r = tid - 48 * n, u = r / 3, m = r - 3 * u;
        float v = g_K[2 * u] * x[n * 6 + m] + g_K[2 * u + 1] * x[n * 6 + 3 + m];
        g_yv[tid] = v; g_yvold[tid] = v;
    }
    if (tid < NN * 6) g_x[tid] = x[tid];
}

/* ---------- node kernel 1: lin1 / sc / si ---------- */
__global__ void k_node1(int l, const int* __restrict__ ntype,
                        const float* __restrict__ siWs, const float* __restrict__ siWv) {
    int n = blockIdx.x, tid = threadIdx.x;
    __shared__ float sy[64], sv[48];
    if (tid < 64) sy[tid] = g_ys[n * 64 + tid];
    if (tid < 48) sv[tid] = g_yv[n * 48 + tid];
    __syncthreads();
    int t = ntype[n];
    size_t base = (size_t)l * NT + t;
    const float* w = cw_scs + base * 5120;
    float acc = 0.f;
#pragma unroll 8
    for (int i = 0; i < 64; i++) acc += sy[i] * w[i * 80 + tid];
    g_scs[n * 80 + tid] = acc;
    if (tid < 64) {
        w = cw_l1s + base * 4096;
        acc = 0.f;
#pragma unroll 8
        for (int i = 0; i < 64; i++) acc += sy[i] * w[i * 64 + tid];
        g_fs[n * 64 + tid] = acc;
        const float* ws = siWs + (size_t)l * 4096 + tid * 64;
        acc = 0.f;
#pragma unroll 8
        for (int i = 0; i < 64; i++) acc += sy[i] * ws[i];
        g_sis[n * 64 + tid] = acc * 0.125f;
    }
    if (tid < 48) {
        int u = tid / 3, m = tid - 3 * u;
        w = cw_l1v + base * 256;
        acc = 0.f;
#pragma unroll
        for (int i = 0; i < 16; i++) acc += w[i * 16 + u] * sv[3 * i + m];
        g_fvv[n * 48 + tid] = acc;
        w = cw_scv + base * 256;
        acc = 0.f;
#pragma unroll
        for (int i = 0; i < 16; i++) acc += w[i * 16 + u] * sv[3 * i + m];
        g_scv[n * 48 + tid] = acc;
        const float* wv = siWv + (size_t)l * 256;
        acc = 0.f;
#pragma unroll
        for (int i = 0; i < 16; i++) acc += wv[u * 16 + i] * sv[3 * i + m];
        g_siv[n * 48 + tid] = acc * 0.25f;
    }
}

/* ---------- zero mid accumulators ---------- */
__global__ void k_zero() {
    int tid = blockIdx.x * 256 + threadIdx.x;
    if (tid < NN * 240) g_midv[tid] = 0.f;
    if (tid < NN * 16) g_mids[tid] = 0.f;
}

/* ---------- fused edge kernel: geom + radial MLP (f32x2) + TP + scatter ---------- */
#define WSLOT 208
__global__ void __launch_bounds__(256)
k_edge(const int* __restrict__ esrc, const int* __restrict__ edst,
       const float* __restrict__ W1, const float* __restrict__ b1,
       const float* __restrict__ W2, const float* __restrict__ b2,
       const float* __restrict__ W3, const float* __restrict__ b3) {
    extern __shared__ float sm[];
    float* sW1p = sm;            /* 1024 : pairs (o,o+32) interleaved, [k][lane] */
    float* sB1p = sm + 1024;     /* 64   : paired biases */
    float* sW2p = sm + 1088;     /* 4096 : pairs */
    float* sB2p = sm + 5184;     /* 64   */
    float* sW3 = sm + 5248;      /* 12288: original layout (pairs already adjacent) */
    float* sB3 = sm + 17536;     /* 192  */
    int tid = threadIdx.x, wid = tid >> 5, lane = tid & 31;
    float* wsm = sm + 17728 + wid * WSLOT;
    float* ef = wsm;             /* 16 */
    float* h1 = wsm + 16;        /* 64 */
    float* h2s = wsm + 80;       /* 64 */
    float* aa = wsm + 144;       /* 6 */
    float* vs = wsm + 150;       /* 48 */
    float* dd = wsm + 198;       /* 6 */

    /* stage weights: W1/W2 permuted into (o, o+32) pairs */
    for (int i = tid; i < 512; i += 256) {
        int k = i >> 5, j = i & 31;
        sW1p[2 * i] = W1[k * 64 + j];
        sW1p[2 * i + 1] = W1[k * 64 + j + 32];
    }
    for (int i = tid; i < 2048; i += 256) {
        int k = i >> 5, j = i & 31;
        sW2p[2 * i] = W2[k * 64 + j];
        sW2p[2 * i + 1] = W2[k * 64 + j + 32];
    }
    for (int i = tid; i < 12288; i += 256) sW3[i] = W3[i];
    if (tid < 32) {
        sB1p[2 * tid] = b1[tid]; sB1p[2 * tid + 1] = b1[tid + 32];
        sB2p[2 * tid] = b2[tid]; sB2p[2 * tid + 1] = b2[tid + 32];
    }
    if (tid < 192) sB3[tid] = b3[tid];
    __syncthreads();

    const unsigned long long* uW1 = (const unsigned long long*)sW1p;
    const unsigned long long* uB1 = (const unsigned long long*)sB1p;
    const unsigned long long* uW2 = (const unsigned long long*)sW2p;
    const unsigned long long* uB2 = (const unsigned long long*)sB2p;
    const unsigned long long* uW3 = (const unsigned long long*)sW3;
    const unsigned long long* uB3 = (const unsigned long long*)sB3;

    for (int e = blockIdx.x * 8 + wid; e < NE; e += gridDim.x * 8) {
        __syncwarp();
        int src = esrc[e], dst = edst[e];
        if (lane < 6) dd[lane] = g_x[src * 6 + lane] - g_x[dst * 6 + lane];
        __syncwarp();
        float d0 = dd[0], d1 = dd[1], d2 = dd[2], d3 = dd[3], d4 = dd[4], d5 = dd[5];
        float rr = sqrtf(d0 * d0 + d1 * d1 + d2 * d2);
        float rv = sqrtf(d3 * d3 + d4 * d4 + d5 * d5);
        float cr = cutf_(rr), cv = cutf_(rv);
        if (cr == 0.f && cv == 0.f) continue;
        if (lane < 3) aa[lane] = cr * SQRT3_F / rr * dd[lane];
        else if (lane < 6) aa[lane] = cv * SQRT3_F / rv * dd[lane];
        if (lane < 8) ef[lane] = EF_C * sinf((float)(lane + 1) * PI_F * rr / MR_) / rr;
        else if (lane < 16) ef[lane] = EF_C * sinf((float)(lane - 7) * PI_F * rv / MR_) / rv;
        __syncwarp();
        /* layer 1 (f32x2, outputs lane & lane+32) */
        unsigned long long acc = uB1[lane];
#pragma unroll
        for (int k = 0; k < 16; k++) {
            unsigned long long f2 = pack2_(ef[k]);
            ffma2_(acc, f2, uW1[k * 32 + lane]);
        }
        {
            float2 h = unpack2_(acc);
            h1[lane] = silu_(h.x); h1[lane + 32] = silu_(h.y);
        }
        __syncwarp();
        /* layer 2, plus stage v_src */
        acc = uB2[lane];
#pragma unroll 8
        for (int k = 0; k < 64; k++) {
            unsigned long long f2 = pack2_(h1[k]);
            ffma2_(acc, f2, uW2[k * 32 + lane]);
        }
        {
            float2 h = unpack2_(acc);
            h2s[lane] = silu_(h.x); h2s[lane + 32] = silu_(h.y);
        }
        if (lane < 24) {
            vs[2 * lane] = g_fvv[src * 48 + 2 * lane];
            vs[2 * lane + 1] = g_fvv[src * 48 + 2 * lane + 1];
        }
        __syncwarp();
        /* layer 3: three f32x2 output pairs per lane:
           pair0=(2l,2l+1), pair1=(64+2l,65+2l), pair2=(o4,o5) == f2 index 64+lane */
        unsigned long long a0 = uB3[lane], a1 = uB3[32 + lane], a2 = uB3[64 + lane];
#pragma unroll 8
        for (int k = 0; k < 64; k++) {
            unsigned long long f2 = pack2_(h2s[k]);
            const unsigned long long* row = uW3 + k * 96;
            ffma2_(a0, f2, row[lane]);
            ffma2_(a1, f2, row[32 + lane]);
            ffma2_(a2, f2, row[64 + lane]);
        }
        float2 pA = unpack2_(a0), pB = unpack2_(a1), pC = unpack2_(a2);
        float wA0 = pA.x, wA1 = pA.y, wA2 = pB.x, wA3 = pB.y, w4 = pC.x, w5 = pC.y;
        /* tensor products + scatter */
        float s0 = g_fs[src * 64 + lane], s1 = g_fs[src * 64 + lane + 32];
        float a00 = aa[0], a01 = aa[1], a02 = aa[2];
        float a10 = aa[3], a11 = aa[4], a12 = aa[5];
        float* mv = &g_midv[dst * 240];
        float c0 = s0 * INV_SQRT2;
        atomicAdd(&mv[3 * lane + 0], c0 * (wA0 * a00 + wA1 * a10));
        atomicAdd(&mv[3 * lane + 1], c0 * (wA0 * a01 + wA1 * a11));
        atomicAdd(&mv[3 * lane + 2], c0 * (wA0 * a02 + wA1 * a12));
        float c1 = s1 * INV_SQRT2;
        int u2 = lane + 32;
        atomicAdd(&mv[3 * u2 + 0], c1 * (wA2 * a00 + wA3 * a10));
        atomicAdd(&mv[3 * u2 + 1], c1 * (wA2 * a01 + wA3 * a11));
        atomicAdd(&mv[3 * u2 + 2], c1 * (wA2 * a02 + wA3 * a12));
        if (lane < 16) {
            float v0 = vs[3 * lane], v1 = vs[3 * lane + 1], v2 = vs[3 * lane + 2];
            float dA = v0 * a00 + v1 * a01 + v2 * a02;
            float dB = v0 * a10 + v1 * a11 + v2 * a12;
            atomicAdd(&g_mids[dst * 16 + lane], (w4 * dA + w5 * dB) * INV_SQRT6);
        } else {
            int u = lane - 16;
            float v0 = vs[3 * u], v1 = vs[3 * u + 1], v2 = vs[3 * u + 2];
            float cx0 = v1 * a02 - v2 * a01, cy0 = v2 * a00 - v0 * a02, cz0 = v0 * a01 - v1 * a00;
            float cx1 = v1 * a12 - v2 * a11, cy1 = v2 * a10 - v0 * a12, cz1 = v0 * a11 - v1 * a10;
            atomicAdd(&mv[(64 + u) * 3 + 0], 0.5f * (w4 * cx0 + w5 * cx1));
            atomicAdd(&mv[(64 + u) * 3 + 1], 0.5f * (w4 * cy0 + w5 * cy1));
            atomicAdd(&mv[(64 + u) * 3 + 2], 0.5f * (w4 * cz0 + w5 * cz1));
        }
    }
}

/* ---------- node kernel 2: lin2 + gate + leapfrog + project ---------- */
__global__ void k_node2(int l, const int* __restrict__ ntype,
                        const float* __restrict__ hv, const float* __restrict__ mixv) {
    int n = blockIdx.x, tid = threadIdx.x;
    __shared__ float smids[16], smidv[240], sg[80], snv[48];
    if (tid < 16) smids[tid] = g_mids[n * 16 + tid];
    for (int i = tid; i < 240; i += 80) smidv[i] = g_midv[n * 240 + i];
    __syncthreads();
    int t = ntype[n];
    size_t base = (size_t)l * NT + t;
    float h2 = hv[l] * hv[l], mx = mixv[l];
    const float* w = cw_l2s + base * 1280;
    float acc = 0.f;
#pragma unroll
    for (int i = 0; i < 16; i++) acc += smids[i] * w[i * 80 + tid];
    float conv_s = C_S * g_scs[n * 80 + tid] + C_X * acc;
    sg[tid] = conv_s;
    __syncthreads();
    if (tid < 64) {
        float gns = silu_(conv_s);
        float yo = g_ysold[n * 64 + tid], yc = g_ys[n * 64 + tid];
        float ns = 2.f * yc - yo + h2 * (mx * gns + (mx - 1.f) * g_sis[n * 64 + tid]);
        g_ysold[n * 64 + tid] = yc; g_ys[n * 64 + tid] = ns;
    }
    if (tid < 48) {
        int u = tid / 3, m = tid - 3 * u;
        const float* wv = cw_l2v + base * 1280;
        acc = 0.f;
#pragma unroll 8
        for (int i = 0; i < 80; i++) acc += wv[i * 16 + u] * smidv[3 * i + m];
        float conv_v = C_S * g_scv[n * 48 + tid] + C_X * acc;
        float gnv = sigm_(sg[64 + u]) * conv_v;
        float yo = g_yvold[n * 48 + tid], yc = g_yv[n * 48 + tid];
        float nv = 2.f * yc - yo + h2 * (mx * gnv + (mx - 1.f) * g_siv[n * 48 + tid]);
        g_yvold[n * 48 + tid] = yc; g_yv[n * 48 + tid] = nv;
        snv[tid] = nv;
    }
    __syncthreads();
    if (tid < 6) {
        int i = tid / 3, m = tid - 3 * i;
        float s = 0.f;
#pragma unroll
        for (int u = 0; u < 16; u++) s += g_K[2 * u + i] * snv[3 * u + m];
        g_x[n * 6 + tid] = s;
    }
}

__global__ void k_copyout(float* __restrict__ out) {
    int tid = blockIdx.x * 256 + threadIdx.x;
    if (tid < NN * 6) out[tid] = g_x[tid];
}

/* ---------- launch ---------- */
extern "C" void kernel_launch(void* const* d_in, const int* in_sizes, int n_in,
                              void* d_out, int out_size) {
    const float* x = (const float*)d_in[0];
    const int* node_attr = (const int*)d_in[2];
    const int* esrc = (const int*)d_in[3];
    const int* edst = (const int*)d_in[4];
    const float* emb = (const float*)d_in[5];
    const float* PU = (const float*)d_in[6];
    const float* hv = (const float*)d_in[7];
    const float* mixv = (const float*)d_in[8];
    const float* siWs = (const float*)d_in[9];
    const float* siWv = (const float*)d_in[10];
    const float* scWs = (const float*)d_in[11];
    const float* scWv = (const float*)d_in[12];
    const float* l1Ws = (const float*)d_in[13];
    const float* l1Wv = (const float*)d_in[14];
    const float* l2Ws = (const float*)d_in[15];
    const float* l2Wv = (const float*)d_in[16];
    const float* fW1 = (const float*)d_in[17];
    const float* fb1 = (const float*)d_in[18];
    const float* fW2 = (const float*)d_in[19];
    const float* fb2 = (const float*)d_in[20];
    const float* fW3 = (const float*)d_in[21];
    const float* fb3 = (const float*)d_in[22];

    static int smem_set = 0;
    const int EDGE_SMEM = (17728 + 8 * WSLOT) * 4;
    if (!smem_set) {
        cudaFuncSetAttribute(k_edge, cudaFuncAttributeMaxDynamicSharedMemorySize, EDGE_SMEM);
        smem_set = 1;
    }

    k_newton<<<1, 1>>>(PU);
    float n2048 = 1.f / sqrtf(2048.f), n512 = 1.f / sqrtf(512.f);
    float n2_l2s = 1.f / sqrtf(512.f * 32.f), n2_l2v = 1.f / sqrtf(2560.f * 32.f);
    k_contract<<<NLAY * (4096 / 128), 128>>>(l1Ws, emb, 64, 64, n2048, 0);
    k_contract<<<NLAY * (256 / 128), 128>>>(l1Wv, emb, 16, 16, n512, 1);
    k_contract<<<NLAY * (5120 / 128), 128>>>(scWs, emb, 80, 64, n2048, 2);
    k_contract<<<NLAY * (256 / 128), 128>>>(scWv, emb, 16, 16, n512, 3);
    k_contract<<<NLAY * (1280 / 128), 128>>>(l2Ws, emb, 80, 16, n2_l2s, 4);
    k_contract<<<NLAY * (1280 / 128), 128>>>(l2Wv, emb, 16, 80, n2_l2v, 5);
    k_init<<<(NN * 64 + 255) / 256, 256>>>(x);

    for (int l = 0; l < NLAY; l++) {
        k_node1<<<NN, 80>>>(l, node_attr, siWs, siWv);
        k_zero<<<(NN * 240 + 255) / 256, 256>>>();
        k_edge<<<296, 256, EDGE_SMEM>>>(esrc, edst,
                                        fW1 + (size_t)l * 1024, fb1 + (size_t)l * 64,
                                        fW2 + (size_t)l * 4096, fb2 + (size_t)l * 64,
                                        fW3 + (size_t)l * 12288, fb3 + (size_t)l * 192);
        k_node2<<<NN, 80>>>(l, node_attr, hv, mixv);
    }
    k_copyout<<<(NN * 6 + 255) / 256, 256>>>((float*)d_out);
}